// round 6
// baseline (speedup 1.0000x reference)
#include <cuda_runtime.h>

#define THREADS 512
#define ITEMS 16
#define TILE (THREADS * ITEMS)   // 8192
#define MAX_TILES 65536
#define NWARPS (THREADS / 32)

// decoupled-lookback state: high 32 bits = epoch*4 + status (1=aggregate, 2=prefix),
// low 32 bits = fp32 value bits. Flag+value share one 64-bit word => relaxed ld/st OK.
// Epoch versioning => no init kernel: stale words decode as invalid this epoch.
__device__ unsigned long long g_state[MAX_TILES];
__device__ unsigned int g_ticket;   // zero-init once; monotonic across graph replays

__device__ __forceinline__ unsigned long long ld_state(const unsigned long long* p) {
    unsigned long long v;
    asm volatile("ld.global.cg.u64 %0, [%1];" : "=l"(v) : "l"(p));
    return v;
}
__device__ __forceinline__ void st_state(unsigned long long* p, unsigned long long v) {
    asm volatile("st.global.cg.u64 [%0], %1;" :: "l"(p), "l"(v) : "memory");
}
__device__ __forceinline__ unsigned long long pack_sv(unsigned st, float v) {
    return ((unsigned long long)st << 32) | (unsigned long long)__float_as_uint(v);
}
__device__ __forceinline__ float warp_sum(float v) {
    #pragma unroll
    for (int o = 16; o; o >>= 1) v += __shfl_xor_sync(0xFFFFFFFFu, v, o);
    return v;
}

__global__ void __launch_bounds__(THREADS, 2) rtam_scan(
    const int* __restrict__ ann,
    const float* __restrict__ p_origin,
    const float* __restrict__ p_bd,
    const float* __restrict__ p_d,
    const float* __restrict__ p_s,
    const float* __restrict__ p_inc,
    const float* __restrict__ p_bi,
    float* __restrict__ out,
    int n, int ntiles)
{
    __shared__ float s_table[8];
    __shared__ float s_warp[NWARPS];
    __shared__ unsigned s_ticket;
    // block-wide lookback scratch
    __shared__ float s_fullsum[NWARPS], s_prefsum[NWARPS];
    __shared__ int   s_fullok[NWARPS], s_haspref[NWARPS];
    __shared__ float s_excl;
    __shared__ int   s_look, s_done;

    const int tid  = threadIdx.x;
    const int lane = tid & 31;
    const int wid  = tid >> 5;

    if (tid == 0) {
        s_ticket = atomicAdd(&g_ticket, 1u);
        const float EPS = 0.05f;
        float bd = *p_bd, d = *p_d, s = *p_s, inc = *p_inc, bi = *p_bi;
        s_table[0] = 0.f;
        s_table[1] = fminf(bd, fminf(0.f, d)) - EPS;                 // big decrease
        s_table[2] = fminf(fmaxf(d, bd + EPS), -EPS);                // decrease (clip)
        s_table[3] = s;                                              // same
        s_table[4] = fminf(fmaxf(inc, EPS), bi - EPS);               // increase (clip)
        s_table[5] = fmaxf(bi, fmaxf(0.f, inc) + EPS);               // big increase
        s_table[6] = *p_origin;
    }
    __syncthreads();

    const unsigned ticket = s_ticket;
    const unsigned tile   = ticket % (unsigned)ntiles;
    const unsigned epoch  = ticket / (unsigned)ntiles;
    const unsigned eb     = epoch * 4u;               // status base for this epoch
    const float origin    = s_table[6];
    const long long base  = (long long)tile * TILE;
    const long long rem64 = (long long)n - base;
    const int remaining   = (rem64 > (long long)TILE) ? TILE : (int)rem64;

    // ---- per-thread blocked load + serial inclusive scan (16 items) ----
    float vals[ITEMS];
    float run = 0.f;

    if (remaining >= TILE) {
        const int4* in4 = (const int4*)(ann + base);
        #pragma unroll
        for (int k = 0; k < ITEMS / 4; k++) {
            int4 c = in4[tid * (ITEMS / 4) + k];
            run += s_table[c.x]; vals[4 * k + 0] = run;
            run += s_table[c.y]; vals[4 * k + 1] = run;
            run += s_table[c.z]; vals[4 * k + 2] = run;
            run += s_table[c.w]; vals[4 * k + 3] = run;
        }
    } else {
        #pragma unroll
        for (int j = 0; j < ITEMS; j++) {
            long long idx = base + (long long)tid * ITEMS + j;
            float c = (idx < (long long)n) ? s_table[ann[idx]] : 0.f;
            run += c;
            vals[j] = run;
        }
    }

    // ---- block scan of per-thread sums (warp shfl + smem across warps) ----
    const float tsum = run;
    float x = tsum;
    #pragma unroll
    for (int o = 1; o < 32; o <<= 1) {
        float y = __shfl_up_sync(0xFFFFFFFFu, x, o);
        if (lane >= o) x += y;
    }
    if (lane == 31) s_warp[wid] = x;
    __syncthreads();
    if (wid == 0) {
        float w = (lane < NWARPS) ? s_warp[lane] : 0.f;
        #pragma unroll
        for (int o = 1; o < NWARPS; o <<= 1) {
            float y = __shfl_up_sync(0xFFFFFFFFu, w, o);
            if (lane >= o) w += y;
        }
        if (lane < NWARPS) s_warp[lane] = w;
    }
    __syncthreads();

    const float block_agg   = s_warp[NWARPS - 1];
    const float thread_excl = (wid > 0 ? s_warp[wid - 1] : 0.f) + (x - tsum);

    // ---- publish aggregate immediately ----
    if (tid == 0) {
        st_state(&g_state[tile], pack_sv(eb + (tile == 0 ? 2u : 1u), block_agg));
        s_excl = 0.f;
        s_done = (tile == 0) ? 1 : 0;
        s_look = (int)tile - 1;
    }
    __syncthreads();

    // ---- BLOCK-WIDE decoupled lookback: 512 predecessors per round ----
    // warp w covers offsets [32w, 32w+31] behind s_look (warp 0 = nearest).
    if (!s_done) {
        for (;;) {
            const int look = s_look;          // stable between barriers
            const int idx  = look - tid;
            unsigned d; float val;
            if (idx >= 0) {
                unsigned long long v = ld_state(&g_state[idx]);
                d   = (unsigned)(v >> 32) - eb;   // stale epoch -> huge value
                val = __uint_as_float((unsigned)(v & 0xFFFFFFFFULL));
            } else {
                d = 2u; val = 0.f;
            }
            const unsigned pm = __ballot_sync(0xFFFFFFFFu, d == 2u);
            const unsigned am = __ballot_sync(0xFFFFFFFFu, d == 1u || d == 2u);

            int haspref = 0; float prefsum = 0.f;
            if (pm) {
                const int p = __ffs(pm) - 1;  // nearest predecessor with full prefix
                const unsigned need = (p == 31) ? 0xFFFFFFFFu : ((1u << (p + 1)) - 1u);
                if ((am & need) == need) {
                    haspref = 1;
                    prefsum = warp_sum((lane <= p) ? val : 0.f);
                }
            }
            const int fullok = (am == 0xFFFFFFFFu);
            const float fullsum = fullok ? warp_sum(val) : 0.f;

            if (lane == 0) {
                s_fullsum[wid] = fullsum;
                s_prefsum[wid] = prefsum;
                s_fullok[wid]  = fullok;
                s_haspref[wid] = haspref;
            }
            __syncthreads();

            if (tid == 0) {
                float add = 0.f; int found = 0, w;
                for (w = 0; w < NWARPS; w++) {
                    if (s_haspref[w]) { add += s_prefsum[w]; found = 1; break; }
                    if (!s_fullok[w]) break;
                    add += s_fullsum[w];
                }
                if (found) {
                    const float e = s_excl + add;
                    s_excl = e;
                    s_done = 1;
                    st_state(&g_state[tile], pack_sv(eb + 2u, e + block_agg));
                } else {
                    s_excl += add;          // consumed w full windows of aggregates
                    s_look  = look - 32 * w;
                }
            }
            __syncthreads();
            if (s_done) break;
        }
    }

    // pref == out[base + 16*tid]
    const float pref = origin + s_excl + thread_excl;

    // ---- aligned blocked stores: thread t owns out[base+16t .. base+16t+15] ----
    if (remaining >= TILE) {
        float4* o4 = (float4*)(out + base + tid * ITEMS);   // 16B-aligned
        float4 r;
        r.x = pref;                 r.y = pref + vals[0];
        r.z = pref + vals[1];       r.w = pref + vals[2];
        o4[0] = r;
        #pragma unroll
        for (int k = 0; k < 3; k++) {
            r.x = pref + vals[3 + 4 * k];
            r.y = pref + vals[4 + 4 * k];
            r.z = pref + vals[5 + 4 * k];
            r.w = pref + vals[6 + 4 * k];
            o4[1 + k] = r;
        }
        // one slot past this tile's range: out[n] when this is the last full tile
        if (tid == THREADS - 1 && base + TILE == (long long)n)
            out[n] = pref + vals[15];
    } else {
        #pragma unroll
        for (int j = 0; j < ITEMS; j++) {
            int i = tid * ITEMS + j;
            if (i <= remaining)
                out[base + i] = pref + (j ? vals[j - 1] : 0.f);
        }
    }
}

extern "C" void kernel_launch(void* const* d_in, const int* in_sizes, int n_in,
                              void* d_out, int out_size) {
    const int*   ann    = (const int*)d_in[0];
    const float* origin = (const float*)d_in[1];
    const float* bd     = (const float*)d_in[2];
    const float* d      = (const float*)d_in[3];
    const float* s      = (const float*)d_in[4];
    const float* inc    = (const float*)d_in[5];
    const float* bi     = (const float*)d_in[6];
    float* out = (float*)d_out;

    int n = in_sizes[0];
    int ntiles = (n + TILE - 1) / TILE;
    if (ntiles > MAX_TILES) ntiles = MAX_TILES;   // n = 2^25 -> 4096 tiles

    rtam_scan<<<ntiles, THREADS>>>(ann, origin, bd, d, s, inc, bi, out, n, ntiles);
}

// round 7
// speedup vs baseline: 1.9181x; 1.9181x over previous
#include <cuda_runtime.h>

#define THREADS 512
#define ITEMS 16
#define TILE (THREADS * ITEMS)   // 8192
#define MAX_TILES 65536
#define SIDX(i) ((i) + ((i) >> 4))   // smem skew: conflict-free blocked writes

// decoupled-lookback state: high 32 bits = status (0 invalid, 1 aggregate, 2 prefix),
// low 32 bits = fp32 value bits. One 64-bit atomic word => no fence needed.
__device__ unsigned long long g_state[MAX_TILES];
__device__ unsigned int g_ticket;

__global__ void rtam_init(int ntiles) {
    int i = blockIdx.x * blockDim.x + threadIdx.x;
    if (i < ntiles) g_state[i] = 0ULL;
    if (i == 0) g_ticket = 0u;
}

__device__ __forceinline__ unsigned long long pack_sv(unsigned st, float v) {
    return ((unsigned long long)st << 32) | (unsigned long long)__float_as_uint(v);
}

// pure-ALU 5-entry LUT: no shared-memory gather, no bank conflicts
__device__ __forceinline__ float lut5(int c, float t1, float t2, float t3,
                                      float t4, float t5) {
    float a = (c < 2) ? t1 : ((c < 3) ? t2 : t3);   // c == 1,2,3
    float b = (c < 5) ? t4 : t5;                     // c == 4,5
    return (c < 4) ? a : b;
}

__global__ void __launch_bounds__(THREADS, 1) rtam_scan(
    const int* __restrict__ ann,
    const float* __restrict__ p_origin,
    const float* __restrict__ p_bd,
    const float* __restrict__ p_d,
    const float* __restrict__ p_s,
    const float* __restrict__ p_inc,
    const float* __restrict__ p_bi,
    float* __restrict__ out,
    int n)
{
    __shared__ float s_out[TILE + TILE / 16];   // skewed
    __shared__ float s_table[8];
    __shared__ float s_warp[THREADS / 32];
    __shared__ float s_excl;
    __shared__ unsigned s_tile;

    const int tid  = threadIdx.x;
    const int lane = tid & 31;
    const int wid  = tid >> 5;

    if (tid == 0) {
        s_tile = atomicAdd(&g_ticket, 1u);
        const float EPS = 0.05f;
        float bd = *p_bd, d = *p_d, s = *p_s, inc = *p_inc, bi = *p_bi;
        s_table[0] = 0.f;
        s_table[1] = fminf(bd, fminf(0.f, d)) - EPS;                 // big decrease
        s_table[2] = fminf(fmaxf(d, bd + EPS), -EPS);                // decrease (clip)
        s_table[3] = s;                                              // same
        s_table[4] = fminf(fmaxf(inc, EPS), bi - EPS);               // increase (clip)
        s_table[5] = fmaxf(bi, fmaxf(0.f, inc) + EPS);               // big increase
        s_table[6] = *p_origin;
    }
    __syncthreads();

    const unsigned tile = s_tile;
    const float origin  = s_table[6];
    // table values into registers once; broadcast LDS, conflict-free
    const float t1 = s_table[1], t2 = s_table[2], t3 = s_table[3];
    const float t4 = s_table[4], t5 = s_table[5];

    const long long base = (long long)tile * TILE;
    const long long rem64 = (long long)n - base;
    const int remaining = (rem64 > (long long)TILE) ? TILE : (int)rem64;

    // ---- per-thread blocked load + serial inclusive scan (16 items) ----
    float vals[ITEMS];
    float run = 0.f;

    if (remaining >= TILE) {
        const int4* in4 = (const int4*)(ann + base);
        #pragma unroll
        for (int k = 0; k < ITEMS / 4; k++) {
            int4 c = in4[tid * (ITEMS / 4) + k];
            run += lut5(c.x, t1, t2, t3, t4, t5); vals[4 * k + 0] = run;
            run += lut5(c.y, t1, t2, t3, t4, t5); vals[4 * k + 1] = run;
            run += lut5(c.z, t1, t2, t3, t4, t5); vals[4 * k + 2] = run;
            run += lut5(c.w, t1, t2, t3, t4, t5); vals[4 * k + 3] = run;
        }
    } else {
        #pragma unroll
        for (int j = 0; j < ITEMS; j++) {
            long long idx = base + (long long)tid * ITEMS + j;
            float c = 0.f;
            if (idx < (long long)n) c = lut5(ann[idx], t1, t2, t3, t4, t5);
            run += c;
            vals[j] = run;
        }
    }

    // ---- block scan of per-thread sums (warp shfl + smem across 16 warps) ----
    const float tsum = run;
    float x = tsum;
    #pragma unroll
    for (int o = 1; o < 32; o <<= 1) {
        float y = __shfl_up_sync(0xFFFFFFFFu, x, o);
        if (lane >= o) x += y;
    }
    if (lane == 31) s_warp[wid] = x;
    __syncthreads();
    if (wid == 0) {
        float w = (lane < THREADS / 32) ? s_warp[lane] : 0.f;
        #pragma unroll
        for (int o = 1; o < THREADS / 32; o <<= 1) {
            float y = __shfl_up_sync(0xFFFFFFFFu, w, o);
            if (lane >= o) w += y;
        }
        if (lane < THREADS / 32) s_warp[lane] = w;
    }
    __syncthreads();

    const float block_agg   = s_warp[THREADS / 32 - 1];
    const float thread_excl = (wid > 0 ? s_warp[wid - 1] : 0.f) + (x - tsum);

    // ---- warp 0: publish aggregate, decoupled lookback, publish prefix ----
    if (wid == 0) {
        if (lane == 0)
            atomicExch(&g_state[tile], pack_sv(tile == 0 ? 2u : 1u, block_agg));

        float excl = 0.f;
        if (tile > 0) {
            int look = (int)tile - 1;
            for (;;) {
                int idx = look - lane;
                unsigned long long v = (idx >= 0) ? atomicAdd(&g_state[idx], 0ULL)
                                                  : pack_sv(2u, 0.f);
                unsigned st = (unsigned)(v >> 32);
                float val = __uint_as_float((unsigned)(v & 0xFFFFFFFFULL));
                unsigned pm = __ballot_sync(0xFFFFFFFFu, st == 2u);
                unsigned am = __ballot_sync(0xFFFFFFFFu, st >= 1u);
                if (pm) {
                    int p = __ffs(pm) - 1;   // closest predecessor with a full prefix
                    unsigned need = (p == 31) ? 0xFFFFFFFFu : ((1u << (p + 1)) - 1u);
                    if ((am & need) == need) {
                        float contrib = (lane <= p) ? val : 0.f;
                        #pragma unroll
                        for (int o = 16; o; o >>= 1)
                            contrib += __shfl_xor_sync(0xFFFFFFFFu, contrib, o);
                        excl += contrib;
                        break;
                    }
                } else if (am == 0xFFFFFFFFu) {
                    float contrib = val;     // window of 32 aggregates, keep walking
                    #pragma unroll
                    for (int o = 16; o; o >>= 1)
                        contrib += __shfl_xor_sync(0xFFFFFFFFu, contrib, o);
                    excl += contrib;
                    look -= 32;
                }
                // else: spin until predecessors publish
            }
            if (lane == 0)
                atomicExch(&g_state[tile], pack_sv(2u, excl + block_agg));
        }
        if (lane == 0) s_excl = excl;
    }

    // ---- stage tile-local results to skewed smem (overlaps lookback) ----
    #pragma unroll
    for (int j = 0; j < ITEMS; j++)
        s_out[SIDX(tid * ITEMS + j)] = thread_excl + vals[j];
    __syncthreads();

    const float ofs = origin + s_excl;

    // ---- coalesced, aligned store of out[base+1 .. base+remaining] ----
    if (remaining >= TILE) {
        float* op = out + base;                 // 16B-aligned (base % 8192 == 0)
        if (tid < 3)  op[1 + tid] = ofs + s_out[SIDX(tid)];       // head: out[base+1..3]
        if (tid == 3) op[TILE]    = ofs + s_out[SIDX(TILE - 1)];  // tail: out[base+TILE]
        float4* o4 = (float4*)(op + 4);         // 16B-aligned
        const int NV = (TILE - 4) / 4;          // 2047 vectors covering smem i = 3..8190
        for (int v = tid; v < NV; v += THREADS) {
            int i = 3 + 4 * v;
            float4 r;
            r.x = ofs + s_out[SIDX(i + 0)];
            r.y = ofs + s_out[SIDX(i + 1)];
            r.z = ofs + s_out[SIDX(i + 2)];
            r.w = ofs + s_out[SIDX(i + 3)];
            o4[v] = r;
        }
    } else {
        for (int i = tid; i < remaining; i += THREADS)
            out[base + 1 + i] = ofs + s_out[SIDX(i)];
    }

    if (tile == 0 && tid == 0) out[0] = origin;
}

extern "C" void kernel_launch(void* const* d_in, const int* in_sizes, int n_in,
                              void* d_out, int out_size) {
    const int*   ann    = (const int*)d_in[0];
    const float* origin = (const float*)d_in[1];
    const float* bd     = (const float*)d_in[2];
    const float* d      = (const float*)d_in[3];
    const float* s      = (const float*)d_in[4];
    const float* inc    = (const float*)d_in[5];
    const float* bi     = (const float*)d_in[6];
    float* out = (float*)d_out;

    int n = in_sizes[0];
    int ntiles = (n + TILE - 1) / TILE;
    if (ntiles > MAX_TILES) ntiles = MAX_TILES;   // (n = 2^25 -> 4096 tiles)

    rtam_init<<<(ntiles + 255) / 256, 256>>>(ntiles);
    rtam_scan<<<ntiles, THREADS>>>(ann, origin, bd, d, s, inc, bi, out, n);
}